// round 5
// baseline (speedup 1.0000x reference)
#include <cuda_runtime.h>
#include <cstdint>

// Problem dims
#define Bv 32
#define Cv 1024
#define Nv 784
#define Mv 4
#define N4v 196      // Nv/4
#define GR 4         // rows per generation
#define GEN 8        // generations per block
#define BROWS 32     // GR*GEN rows per block
#define CHUNKS 32    // Cv/BROWS
#define GSZ (GR * N4v)   // 784 float4 per generation buffer

// Scratch (device globals — zero-initialized at load; kC restores zeros)
__device__ float  g_invnorm[Bv][Cv];
__device__ float4 g_t[Bv][Mv][N4v];   // RED-accumulated t (400 KB)
__device__ float4 g_h[Bv][N4v];       // h[b,n] = sum_m g/s

__device__ __forceinline__ void cp_async16(uint32_t saddr, const void* gaddr) {
    asm volatile("cp.async.cg.shared.global [%0], [%1], 16;\n" :: "r"(saddr), "l"(gaddr));
}
__device__ __forceinline__ void cp_commit() {
    asm volatile("cp.async.commit_group;\n");
}
template <int N>
__device__ __forceinline__ void cp_wait() {
    asm volatile("cp.async.wait_group %0;\n" :: "n"(N));
}

extern __shared__ float4 smem_dyn[];  // 2 * GSZ float4 = 25088 B

// ---------------------------------------------------------------------------
// kAB: block = (b, 32-row chunk), 8 generations of 4 rows, double-buffered
// cp.async. Per gen: warp-pair norms (2 warps per row, smem combine) then
// 4-row FMA accumulation. Register accumulators flushed via RED atomics.
// ---------------------------------------------------------------------------
__global__ void __launch_bounds__(256) kAB(const float* __restrict__ x,
                                           const float* __restrict__ Wm) {
    __shared__ float4 swsc[GR];
    __shared__ float  spart[8];
    int b = blockIdx.x, ch = blockIdx.y;
    int p0 = ch * BROWS;
    int t = threadIdx.x;
    int warp = t >> 5, lane = t & 31;
    const float4* base = reinterpret_cast<const float4*>(x) + ((size_t)b * Cv + p0) * N4v;
    uint32_t sbase = (uint32_t)__cvta_generic_to_shared(smem_dyn);

    // prefetch generation 0 into buffer 0
#pragma unroll
    for (int k = 0; k < 4; ++k) {
        int i = t + k * 256;
        if (i < GSZ) cp_async16(sbase + i * 16u, base + i);
    }
    cp_commit();

    float4 a0 = {0, 0, 0, 0}, a1 = a0, a2 = a0, a3 = a0;

#pragma unroll
    for (int g = 0; g < GEN; ++g) {
        if (g + 1 < GEN) {
            uint32_t sb = sbase + ((g + 1) & 1) * (GSZ * 16u);
            const float4* gb = base + (g + 1) * GSZ;
#pragma unroll
            for (int k = 0; k < 4; ++k) {
                int i = t + k * 256;
                if (i < GSZ) cp_async16(sb + i * 16u, gb + i);
            }
            cp_commit();
            cp_wait<1>();   // current generation ready
        } else {
            cp_wait<0>();
        }
        __syncthreads();

        float4* cur = smem_dyn + (g & 1) * GSZ;

        // norm partials: warps 2r, 2r+1 split row r by even/odd 32-quad stripes
        {
            int r = warp >> 1, half = warp & 1;
            float s = 0.f;
#pragma unroll
            for (int k = 0; k < 4; ++k) {
                int idx = lane + ((k << 1) + half) * 32;
                if (idx < N4v) {
                    float4 v = cur[r * N4v + idx];
                    s += v.x * v.x + v.y * v.y + v.z * v.z + v.w * v.w;
                }
            }
#pragma unroll
            for (int o = 16; o; o >>= 1) s += __shfl_xor_sync(0xffffffffu, s, o);
            if (lane == 0) spart[warp] = s;
        }
        __syncthreads();

        if (t < GR) {
            float ss = spart[2 * t] + spart[2 * t + 1];
            float inv = 1.0f / fmaxf(sqrtf(ss), 1e-10f);
            int p = p0 + g * GR + t;
            g_invnorm[b][p] = inv;
            float4 w;
            w.x = Wm[0 * Cv + p] * inv;
            w.y = Wm[1 * Cv + p] * inv;
            w.z = Wm[2 * Cv + p] * inv;
            w.w = Wm[3 * Cv + p] * inv;
            swsc[t] = w;
        }
        __syncthreads();

        if (t < N4v) {
#pragma unroll
            for (int r = 0; r < GR; ++r) {
                float4 w  = swsc[r];
                float4 xv = cur[r * N4v + t];
                a0.x = fmaf(w.x, xv.x, a0.x); a0.y = fmaf(w.x, xv.y, a0.y);
                a0.z = fmaf(w.x, xv.z, a0.z); a0.w = fmaf(w.x, xv.w, a0.w);
                a1.x = fmaf(w.y, xv.x, a1.x); a1.y = fmaf(w.y, xv.y, a1.y);
                a1.z = fmaf(w.y, xv.z, a1.z); a1.w = fmaf(w.y, xv.w, a1.w);
                a2.x = fmaf(w.z, xv.x, a2.x); a2.y = fmaf(w.z, xv.y, a2.y);
                a2.z = fmaf(w.z, xv.z, a2.z); a2.w = fmaf(w.z, xv.w, a2.w);
                a3.x = fmaf(w.w, xv.x, a3.x); a3.y = fmaf(w.w, xv.y, a3.y);
                a3.z = fmaf(w.w, xv.z, a3.z); a3.w = fmaf(w.w, xv.w, a3.w);
            }
        }
        __syncthreads();  // buffer fully consumed before next prefetch overwrites
    }

    if (t < N4v) {
        float* d0 = reinterpret_cast<float*>(&g_t[b][0][t]);
        float* d1 = reinterpret_cast<float*>(&g_t[b][1][t]);
        float* d2 = reinterpret_cast<float*>(&g_t[b][2][t]);
        float* d3 = reinterpret_cast<float*>(&g_t[b][3][t]);
        atomicAdd(d0 + 0, a0.x); atomicAdd(d0 + 1, a0.y);
        atomicAdd(d0 + 2, a0.z); atomicAdd(d0 + 3, a0.w);
        atomicAdd(d1 + 0, a1.x); atomicAdd(d1 + 1, a1.y);
        atomicAdd(d1 + 2, a1.z); atomicAdd(d1 + 3, a1.w);
        atomicAdd(d2 + 0, a2.x); atomicAdd(d2 + 1, a2.y);
        atomicAdd(d2 + 2, a2.z); atomicAdd(d2 + 3, a2.w);
        atomicAdd(d3 + 0, a3.x); atomicAdd(d3 + 1, a3.y);
        atomicAdd(d3 + 2, a3.z); atomicAdd(d3 + 3, a3.w);
    }
}

// ---------------------------------------------------------------------------
// kC: one block per b, 224 threads. Sigmoid, per-model sum of g^2,
// h = sum_m g/s; then RE-ZERO g_t for the next call.
// ---------------------------------------------------------------------------
__global__ void __launch_bounds__(224) kC() {
    int b = blockIdx.x;
    int t = threadIdx.x;
    bool valid = (t < N4v);
    float4 gg0 = {0,0,0,0}, gg1 = gg0, gg2 = gg0, gg3 = gg0;
    if (valid) {
        float4 t0 = g_t[b][0][t], t1 = g_t[b][1][t];
        float4 t2 = g_t[b][2][t], t3 = g_t[b][3][t];
        auto sig4 = [](float4 v) {
            float4 r;
            r.x = 1.f / (1.f + __expf(-v.x));
            r.y = 1.f / (1.f + __expf(-v.y));
            r.z = 1.f / (1.f + __expf(-v.z));
            r.w = 1.f / (1.f + __expf(-v.w));
            return r;
        };
        gg0 = sig4(t0); gg1 = sig4(t1); gg2 = sig4(t2); gg3 = sig4(t3);
    }
    float s0 = gg0.x*gg0.x + gg0.y*gg0.y + gg0.z*gg0.z + gg0.w*gg0.w;
    float s1 = gg1.x*gg1.x + gg1.y*gg1.y + gg1.z*gg1.z + gg1.w*gg1.w;
    float s2 = gg2.x*gg2.x + gg2.y*gg2.y + gg2.z*gg2.z + gg2.w*gg2.w;
    float s3 = gg3.x*gg3.x + gg3.y*gg3.y + gg3.z*gg3.z + gg3.w*gg3.w;
#pragma unroll
    for (int o = 16; o; o >>= 1) {
        s0 += __shfl_xor_sync(0xffffffffu, s0, o);
        s1 += __shfl_xor_sync(0xffffffffu, s1, o);
        s2 += __shfl_xor_sync(0xffffffffu, s2, o);
        s3 += __shfl_xor_sync(0xffffffffu, s3, o);
    }
    __shared__ float sm[4];
    if (t < 4) sm[t] = 0.f;
    __syncthreads();
    if ((t & 31) == 0) {
        atomicAdd(&sm[0], s0);
        atomicAdd(&sm[1], s1);
        atomicAdd(&sm[2], s2);
        atomicAdd(&sm[3], s3);
    }
    __syncthreads();
    if (valid) {
        float i0 = 1.f / sm[0], i1 = 1.f / sm[1], i2 = 1.f / sm[2], i3 = 1.f / sm[3];
        float4 h;
        h.x = gg0.x*i0 + gg1.x*i1 + gg2.x*i2 + gg3.x*i3;
        h.y = gg0.y*i0 + gg1.y*i1 + gg2.y*i2 + gg3.y*i3;
        h.z = gg0.z*i0 + gg1.z*i1 + gg2.z*i2 + gg3.z*i3;
        h.w = gg0.w*i0 + gg1.w*i1 + gg2.w*i2 + gg3.w*i3;
        g_h[b][t] = h;
        float4 z = {0, 0, 0, 0};
        g_t[b][0][t] = z; g_t[b][1][t] = z;
        g_t[b][2][t] = z; g_t[b][3][t] = z;
    }
}

// ---------------------------------------------------------------------------
// kD: out[b,p] = invnorm[b,p] * dot(x[b,p,:], h[b,:]). Warp per p; h in smem.
// x is L2-resident after kAB (scratch footprint is tiny), so this runs at L2 BW.
// ---------------------------------------------------------------------------
__global__ void __launch_bounds__(256) kD(const float* __restrict__ x,
                                          float* __restrict__ out) {
    int b = blockIdx.x;
    int warp = threadIdx.x >> 5, lane = threadIdx.x & 31;
    int p = (blockIdx.y << 3) + warp;
    __shared__ float4 sh[N4v];
    if (threadIdx.x < N4v) sh[threadIdx.x] = g_h[b][threadIdx.x];
    __syncthreads();
    const float4* row = reinterpret_cast<const float4*>(x) + ((size_t)b * Cv + p) * N4v;
    float s = 0.f;
#pragma unroll
    for (int k = 0; k < 7; ++k) {
        int idx = lane + k * 32;
        if (idx < N4v) {
            float4 v = row[idx];
            float4 h = sh[idx];
            s += v.x * h.x + v.y * h.y + v.z * h.z + v.w * h.w;
        }
    }
#pragma unroll
    for (int o = 16; o; o >>= 1) s += __shfl_xor_sync(0xffffffffu, s, o);
    if (lane == 0) out[b * Cv + p] = s * g_invnorm[b][p];
}

extern "C" void kernel_launch(void* const* d_in, const int* in_sizes, int n_in,
                              void* d_out, int out_size) {
    const float* x  = (const float*)d_in[0];   // [32,1024,28,28] f32
    const float* Wm = (const float*)d_in[1];   // [4,1,1024] f32
    float* out = (float*)d_out;                // [32,1024] f32

    static const int smem_bytes = 2 * GSZ * sizeof(float4);  // 25088
    cudaFuncSetAttribute(kAB, cudaFuncAttributeMaxDynamicSharedMemorySize, smem_bytes);

    kAB<<<dim3(32, CHUNKS), 256, smem_bytes>>>(x, Wm);
    kC<<<32, 224>>>();
    kD<<<dim3(32, 128), 256>>>(x, out);
}

// round 6
// speedup vs baseline: 1.0458x; 1.0458x over previous
#include <cuda_runtime.h>
#include <cstdint>

// Problem dims
#define Bv 32
#define Cv 1024
#define Nv 784
#define Mv 4
#define N4v 196      // Nv/4
#define KB_ROWS 64   // rows per kB block
#define KB_CH 16     // Cv/KB_ROWS

// Scratch (device globals — zero-initialized at load; kC restores zeros)
__device__ float  g_invnorm[Bv][Cv];
__device__ float4 g_wsc[Bv][Cv];      // Wm[m,p]*invnorm packed over m (512 KB)
__device__ float4 g_t[Bv][Mv][N4v];   // RED-accumulated t (400 KB)
__device__ float4 g_h[Bv][N4v];       // h[b,n] = sum_m g/s

// ---------------------------------------------------------------------------
// kN: pure streaming norm pass (the only DRAM-bound kernel; also warms L2).
// Grid (32, 64), 512 threads = 16 warps; warp w norms row p = ch*16 + w.
// ---------------------------------------------------------------------------
__global__ void __launch_bounds__(512) kN(const float* __restrict__ x,
                                          const float* __restrict__ Wm) {
    int b = blockIdx.x;
    int warp = threadIdx.x >> 5, lane = threadIdx.x & 31;
    int p = (blockIdx.y << 4) + warp;
    const float4* row = reinterpret_cast<const float4*>(x) + ((size_t)b * Cv + p) * N4v;
    float s = 0.f;
#pragma unroll
    for (int k = 0; k < 6; ++k) {         // 6*32 = 192 quads
        float4 v = row[lane + k * 32];
        s += v.x * v.x + v.y * v.y + v.z * v.z + v.w * v.w;
    }
    if (lane + 192 < N4v) {               // tail 4 quads
        float4 v = row[lane + 192];
        s += v.x * v.x + v.y * v.y + v.z * v.z + v.w * v.w;
    }
#pragma unroll
    for (int o = 16; o; o >>= 1) s += __shfl_xor_sync(0xffffffffu, s, o);
    if (lane == 0) {
        float inv = 1.0f / fmaxf(sqrtf(s), 1e-10f);
        g_invnorm[b][p] = inv;
        float4 w;
        w.x = Wm[0 * Cv + p] * inv;
        w.y = Wm[1 * Cv + p] * inv;
        w.z = Wm[2 * Cv + p] * inv;
        w.w = Wm[3 * Cv + p] * inv;
        g_wsc[b][p] = w;
    }
}

// ---------------------------------------------------------------------------
// kB: t-accumulation, reading x from L2 (kN just warmed it).
// Block = (b, 64-row chunk), 224 threads (196 active quad-owners).
// wsc preloaded to smem once; 64-row loop; RED-atomic flush into g_t.
// ---------------------------------------------------------------------------
__global__ void __launch_bounds__(224) kB(const float* __restrict__ x) {
    __shared__ float4 swsc[KB_ROWS];
    int b = blockIdx.x, ch = blockIdx.y;
    int p0 = ch * KB_ROWS;
    int t = threadIdx.x;
    for (int r = t; r < KB_ROWS; r += 224) swsc[r] = g_wsc[b][p0 + r];
    __syncthreads();
    if (t >= N4v) return;
    const float4* base = reinterpret_cast<const float4*>(x) + ((size_t)b * Cv + p0) * N4v;
    float4 a0 = {0, 0, 0, 0}, a1 = a0, a2 = a0, a3 = a0;
#pragma unroll 4
    for (int r = 0; r < KB_ROWS; ++r) {
        float4 w  = swsc[r];
        float4 xv = base[(size_t)r * N4v + t];
        a0.x = fmaf(w.x, xv.x, a0.x); a0.y = fmaf(w.x, xv.y, a0.y);
        a0.z = fmaf(w.x, xv.z, a0.z); a0.w = fmaf(w.x, xv.w, a0.w);
        a1.x = fmaf(w.y, xv.x, a1.x); a1.y = fmaf(w.y, xv.y, a1.y);
        a1.z = fmaf(w.y, xv.z, a1.z); a1.w = fmaf(w.y, xv.w, a1.w);
        a2.x = fmaf(w.z, xv.x, a2.x); a2.y = fmaf(w.z, xv.y, a2.y);
        a2.z = fmaf(w.z, xv.z, a2.z); a2.w = fmaf(w.z, xv.w, a2.w);
        a3.x = fmaf(w.w, xv.x, a3.x); a3.y = fmaf(w.w, xv.y, a3.y);
        a3.z = fmaf(w.w, xv.z, a3.z); a3.w = fmaf(w.w, xv.w, a3.w);
    }
    float* d0 = reinterpret_cast<float*>(&g_t[b][0][t]);
    float* d1 = reinterpret_cast<float*>(&g_t[b][1][t]);
    float* d2 = reinterpret_cast<float*>(&g_t[b][2][t]);
    float* d3 = reinterpret_cast<float*>(&g_t[b][3][t]);
    atomicAdd(d0 + 0, a0.x); atomicAdd(d0 + 1, a0.y);
    atomicAdd(d0 + 2, a0.z); atomicAdd(d0 + 3, a0.w);
    atomicAdd(d1 + 0, a1.x); atomicAdd(d1 + 1, a1.y);
    atomicAdd(d1 + 2, a1.z); atomicAdd(d1 + 3, a1.w);
    atomicAdd(d2 + 0, a2.x); atomicAdd(d2 + 1, a2.y);
    atomicAdd(d2 + 2, a2.z); atomicAdd(d2 + 3, a2.w);
    atomicAdd(d3 + 0, a3.x); atomicAdd(d3 + 1, a3.y);
    atomicAdd(d3 + 2, a3.z); atomicAdd(d3 + 3, a3.w);
}

// ---------------------------------------------------------------------------
// kC: one block per b, 224 threads. Sigmoid, per-model sum of g^2,
// h = sum_m g/s; then RE-ZERO g_t for the next call.
// ---------------------------------------------------------------------------
__global__ void __launch_bounds__(224) kC() {
    int b = blockIdx.x;
    int t = threadIdx.x;
    bool valid = (t < N4v);
    float4 gg0 = {0,0,0,0}, gg1 = gg0, gg2 = gg0, gg3 = gg0;
    if (valid) {
        float4 t0 = g_t[b][0][t], t1 = g_t[b][1][t];
        float4 t2 = g_t[b][2][t], t3 = g_t[b][3][t];
        auto sig4 = [](float4 v) {
            float4 r;
            r.x = 1.f / (1.f + __expf(-v.x));
            r.y = 1.f / (1.f + __expf(-v.y));
            r.z = 1.f / (1.f + __expf(-v.z));
            r.w = 1.f / (1.f + __expf(-v.w));
            return r;
        };
        gg0 = sig4(t0); gg1 = sig4(t1); gg2 = sig4(t2); gg3 = sig4(t3);
    }
    float s0 = gg0.x*gg0.x + gg0.y*gg0.y + gg0.z*gg0.z + gg0.w*gg0.w;
    float s1 = gg1.x*gg1.x + gg1.y*gg1.y + gg1.z*gg1.z + gg1.w*gg1.w;
    float s2 = gg2.x*gg2.x + gg2.y*gg2.y + gg2.z*gg2.z + gg2.w*gg2.w;
    float s3 = gg3.x*gg3.x + gg3.y*gg3.y + gg3.z*gg3.z + gg3.w*gg3.w;
#pragma unroll
    for (int o = 16; o; o >>= 1) {
        s0 += __shfl_xor_sync(0xffffffffu, s0, o);
        s1 += __shfl_xor_sync(0xffffffffu, s1, o);
        s2 += __shfl_xor_sync(0xffffffffu, s2, o);
        s3 += __shfl_xor_sync(0xffffffffu, s3, o);
    }
    __shared__ float sm[4];
    if (t < 4) sm[t] = 0.f;
    __syncthreads();
    if ((t & 31) == 0) {
        atomicAdd(&sm[0], s0);
        atomicAdd(&sm[1], s1);
        atomicAdd(&sm[2], s2);
        atomicAdd(&sm[3], s3);
    }
    __syncthreads();
    if (valid) {
        float i0 = 1.f / sm[0], i1 = 1.f / sm[1], i2 = 1.f / sm[2], i3 = 1.f / sm[3];
        float4 h;
        h.x = gg0.x*i0 + gg1.x*i1 + gg2.x*i2 + gg3.x*i3;
        h.y = gg0.y*i0 + gg1.y*i1 + gg2.y*i2 + gg3.y*i3;
        h.z = gg0.z*i0 + gg1.z*i1 + gg2.z*i2 + gg3.z*i3;
        h.w = gg0.w*i0 + gg1.w*i1 + gg2.w*i2 + gg3.w*i3;
        g_h[b][t] = h;
        float4 z = {0, 0, 0, 0};
        g_t[b][0][t] = z; g_t[b][1][t] = z;
        g_t[b][2][t] = z; g_t[b][3][t] = z;
    }
}

// ---------------------------------------------------------------------------
// kD: out[b,p] = invnorm[b,p] * dot(x[b,p,:], h[b,:]). Warp per p; h in smem.
// x is L2-resident, runs at L2 bandwidth.
// ---------------------------------------------------------------------------
__global__ void __launch_bounds__(256) kD(const float* __restrict__ x,
                                          float* __restrict__ out) {
    int b = blockIdx.x;
    int warp = threadIdx.x >> 5, lane = threadIdx.x & 31;
    int p = (blockIdx.y << 3) + warp;
    __shared__ float4 sh[N4v];
    if (threadIdx.x < N4v) sh[threadIdx.x] = g_h[b][threadIdx.x];
    __syncthreads();
    const float4* row = reinterpret_cast<const float4*>(x) + ((size_t)b * Cv + p) * N4v;
    float s = 0.f;
#pragma unroll
    for (int k = 0; k < 7; ++k) {
        int idx = lane + k * 32;
        if (idx < N4v) {
            float4 v = row[idx];
            float4 h = sh[idx];
            s += v.x * h.x + v.y * h.y + v.z * h.z + v.w * h.w;
        }
    }
#pragma unroll
    for (int o = 16; o; o >>= 1) s += __shfl_xor_sync(0xffffffffu, s, o);
    if (lane == 0) out[b * Cv + p] = s * g_invnorm[b][p];
}

extern "C" void kernel_launch(void* const* d_in, const int* in_sizes, int n_in,
                              void* d_out, int out_size) {
    const float* x  = (const float*)d_in[0];   // [32,1024,28,28] f32
    const float* Wm = (const float*)d_in[1];   // [4,1,1024] f32
    float* out = (float*)d_out;                // [32,1024] f32

    kN<<<dim3(32, 64), 512>>>(x, Wm);
    kB<<<dim3(32, KB_CH), 224>>>(x);
    kC<<<32, 224>>>();
    kD<<<dim3(32, 128), 256>>>(x, out);
}

// round 8
// speedup vs baseline: 1.1039x; 1.0556x over previous
#include <cuda_runtime.h>
#include <cstdint>

// Problem dims
#define Bv 32
#define Cv 1024
#define Nv 784
#define Mv 4
#define N4v 196      // Nv/4
#define BROWS 32     // rows per kAB block
#define CHUNKS 32    // Cv/BROWS

// Scratch (device globals — zero-initialized at load; kC restores zeros)
__device__ float  g_invnorm[Bv][Cv];
__device__ float4 g_t[Bv][Mv][N4v];   // RED-accumulated t (400 KB)
__device__ float4 g_h[Bv][N4v];       // h[b,n] = sum_m g/s

extern __shared__ float4 sdyn[];      // 100 KB pad: forces 2 CTAs/SM; swsc at front

// ---------------------------------------------------------------------------
// kAB: block = (b, 32-row chunk).
// Phase 1: warp w norms rows 4w..4w+3 with 4 CONCURRENT accumulators (28
//          independent loads in flight) -> DRAM-saturating stream.
// Phase 2: thread-per-quad re-reads the block's 100 KB. With only 2 CTAs/SM
//          (smem pad), chip working set ~30 MB -> phase 2 is L2-hot.
// Flush via RED atomics into g_t.
// ---------------------------------------------------------------------------
__global__ void __launch_bounds__(256) kAB(const float* __restrict__ x,
                                           const float* __restrict__ Wm) {
    float4* swsc = sdyn;  // [BROWS]
    int b = blockIdx.x, ch = blockIdx.y;
    int p0 = ch * BROWS;
    int t = threadIdx.x;
    int warp = t >> 5, lane = t & 31;
    const float4* base = reinterpret_cast<const float4*>(x) + ((size_t)b * Cv + p0) * N4v;

    // ---- Phase 1: 4 concurrent row norms per warp ----
    {
        const float4* r0 = base + (size_t)(4 * warp + 0) * N4v;
        const float4* r1 = base + (size_t)(4 * warp + 1) * N4v;
        const float4* r2 = base + (size_t)(4 * warp + 2) * N4v;
        const float4* r3 = base + (size_t)(4 * warp + 3) * N4v;
        float s0 = 0.f, s1 = 0.f, s2 = 0.f, s3 = 0.f;
#pragma unroll
        for (int k = 0; k < 6; ++k) {      // 6*32 = 192 quads
            int idx = lane + k * 32;
            float4 v0 = r0[idx], v1 = r1[idx], v2 = r2[idx], v3 = r3[idx];
            s0 += v0.x * v0.x + v0.y * v0.y + v0.z * v0.z + v0.w * v0.w;
            s1 += v1.x * v1.x + v1.y * v1.y + v1.z * v1.z + v1.w * v1.w;
            s2 += v2.x * v2.x + v2.y * v2.y + v2.z * v2.z + v2.w * v2.w;
            s3 += v3.x * v3.x + v3.y * v3.y + v3.z * v3.z + v3.w * v3.w;
        }
        if (lane < 4) {                    // tail quads 192..195
            int idx = 192 + lane;
            float4 v0 = r0[idx], v1 = r1[idx], v2 = r2[idx], v3 = r3[idx];
            s0 += v0.x * v0.x + v0.y * v0.y + v0.z * v0.z + v0.w * v0.w;
            s1 += v1.x * v1.x + v1.y * v1.y + v1.z * v1.z + v1.w * v1.w;
            s2 += v2.x * v2.x + v2.y * v2.y + v2.z * v2.z + v2.w * v2.w;
            s3 += v3.x * v3.x + v3.y * v3.y + v3.z * v3.z + v3.w * v3.w;
        }
#pragma unroll
        for (int o = 16; o; o >>= 1) {
            s0 += __shfl_xor_sync(0xffffffffu, s0, o);
            s1 += __shfl_xor_sync(0xffffffffu, s1, o);
            s2 += __shfl_xor_sync(0xffffffffu, s2, o);
            s3 += __shfl_xor_sync(0xffffffffu, s3, o);
        }
        if (lane < 4) {
            float ss = (lane == 0) ? s0 : (lane == 1) ? s1 : (lane == 2) ? s2 : s3;
            float inv = 1.0f / fmaxf(sqrtf(ss), 1e-10f);
            int r = 4 * warp + lane;
            int p = p0 + r;
            g_invnorm[b][p] = inv;
            float4 w;
            w.x = Wm[0 * Cv + p] * inv;
            w.y = Wm[1 * Cv + p] * inv;
            w.z = Wm[2 * Cv + p] * inv;
            w.w = Wm[3 * Cv + p] * inv;
            swsc[r] = w;
        }
    }
    __syncthreads();

    // ---- Phase 2: thread-per-quad, 32-row loop, L2-hot re-reads ----
    if (t < N4v) {
        float4 a0 = {0, 0, 0, 0}, a1 = a0, a2 = a0, a3 = a0;
#pragma unroll 8
        for (int r = 0; r < BROWS; ++r) {
            float4 w  = swsc[r];
            float4 xv = base[(size_t)r * N4v + t];
            a0.x = fmaf(w.x, xv.x, a0.x); a0.y = fmaf(w.x, xv.y, a0.y);
            a0.z = fmaf(w.x, xv.z, a0.z); a0.w = fmaf(w.x, xv.w, a0.w);
            a1.x = fmaf(w.y, xv.x, a1.x); a1.y = fmaf(w.y, xv.y, a1.y);
            a1.z = fmaf(w.y, xv.z, a1.z); a1.w = fmaf(w.y, xv.w, a1.w);
            a2.x = fmaf(w.z, xv.x, a2.x); a2.y = fmaf(w.z, xv.y, a2.y);
            a2.z = fmaf(w.z, xv.z, a2.z); a2.w = fmaf(w.z, xv.w, a2.w);
            a3.x = fmaf(w.w, xv.x, a3.x); a3.y = fmaf(w.w, xv.y, a3.y);
            a3.z = fmaf(w.w, xv.z, a3.z); a3.w = fmaf(w.w, xv.w, a3.w);
        }
        float* d0 = reinterpret_cast<float*>(&g_t[b][0][t]);
        float* d1 = reinterpret_cast<float*>(&g_t[b][1][t]);
        float* d2 = reinterpret_cast<float*>(&g_t[b][2][t]);
        float* d3 = reinterpret_cast<float*>(&g_t[b][3][t]);
        atomicAdd(d0 + 0, a0.x); atomicAdd(d0 + 1, a0.y);
        atomicAdd(d0 + 2, a0.z); atomicAdd(d0 + 3, a0.w);
        atomicAdd(d1 + 0, a1.x); atomicAdd(d1 + 1, a1.y);
        atomicAdd(d1 + 2, a1.z); atomicAdd(d1 + 3, a1.w);
        atomicAdd(d2 + 0, a2.x); atomicAdd(d2 + 1, a2.y);
        atomicAdd(d2 + 2, a2.z); atomicAdd(d2 + 3, a2.w);
        atomicAdd(d3 + 0, a3.x); atomicAdd(d3 + 1, a3.y);
        atomicAdd(d3 + 2, a3.z); atomicAdd(d3 + 3, a3.w);
    }
}

// ---------------------------------------------------------------------------
// kC: one block per b, 224 threads. Sigmoid, per-model sum of g^2,
// h = sum_m g/s; then RE-ZERO g_t for the next call.
// ---------------------------------------------------------------------------
__global__ void __launch_bounds__(224) kC() {
    int b = blockIdx.x;
    int t = threadIdx.x;
    bool valid = (t < N4v);
    float4 gg0 = {0,0,0,0}, gg1 = gg0, gg2 = gg0, gg3 = gg0;
    if (valid) {
        float4 t0 = g_t[b][0][t], t1 = g_t[b][1][t];
        float4 t2 = g_t[b][2][t], t3 = g_t[b][3][t];
        auto sig4 = [](float4 v) {
            float4 r;
            r.x = 1.f / (1.f + __expf(-v.x));
            r.y = 1.f / (1.f + __expf(-v.y));
            r.z = 1.f / (1.f + __expf(-v.z));
            r.w = 1.f / (1.f + __expf(-v.w));
            return r;
        };
        gg0 = sig4(t0); gg1 = sig4(t1); gg2 = sig4(t2); gg3 = sig4(t3);
    }
    float s0 = gg0.x*gg0.x + gg0.y*gg0.y + gg0.z*gg0.z + gg0.w*gg0.w;
    float s1 = gg1.x*gg1.x + gg1.y*gg1.y + gg1.z*gg1.z + gg1.w*gg1.w;
    float s2 = gg2.x*gg2.x + gg2.y*gg2.y + gg2.z*gg2.z + gg2.w*gg2.w;
    float s3 = gg3.x*gg3.x + gg3.y*gg3.y + gg3.z*gg3.z + gg3.w*gg3.w;
#pragma unroll
    for (int o = 16; o; o >>= 1) {
        s0 += __shfl_xor_sync(0xffffffffu, s0, o);
        s1 += __shfl_xor_sync(0xffffffffu, s1, o);
        s2 += __shfl_xor_sync(0xffffffffu, s2, o);
        s3 += __shfl_xor_sync(0xffffffffu, s3, o);
    }
    __shared__ float sm[4];
    if (t < 4) sm[t] = 0.f;
    __syncthreads();
    if ((t & 31) == 0) {
        atomicAdd(&sm[0], s0);
        atomicAdd(&sm[1], s1);
        atomicAdd(&sm[2], s2);
        atomicAdd(&sm[3], s3);
    }
    __syncthreads();
    if (valid) {
        float i0 = 1.f / sm[0], i1 = 1.f / sm[1], i2 = 1.f / sm[2], i3 = 1.f / sm[3];
        float4 h;
        h.x = gg0.x*i0 + gg1.x*i1 + gg2.x*i2 + gg3.x*i3;
        h.y = gg0.y*i0 + gg1.y*i1 + gg2.y*i2 + gg3.y*i3;
        h.z = gg0.z*i0 + gg1.z*i1 + gg2.z*i2 + gg3.z*i3;
        h.w = gg0.w*i0 + gg1.w*i1 + gg2.w*i2 + gg3.w*i3;
        g_h[b][t] = h;
        float4 z = {0, 0, 0, 0};
        g_t[b][0][t] = z; g_t[b][1][t] = z;
        g_t[b][2][t] = z; g_t[b][3][t] = z;
    }
}

// ---------------------------------------------------------------------------
// kD: out[b,p] = invnorm[b,p] * dot(x[b,p,:], h[b,:]). Warp per p; h in smem.
// ---------------------------------------------------------------------------
__global__ void __launch_bounds__(256) kD(const float* __restrict__ x,
                                          float* __restrict__ out) {
    int b = blockIdx.x;
    int warp = threadIdx.x >> 5, lane = threadIdx.x & 31;
    int p = (blockIdx.y << 3) + warp;
    __shared__ float4 sh[N4v];
    if (threadIdx.x < N4v) sh[threadIdx.x] = g_h[b][threadIdx.x];
    __syncthreads();
    const float4* row = reinterpret_cast<const float4*>(x) + ((size_t)b * Cv + p) * N4v;
    float s = 0.f;
#pragma unroll
    for (int k = 0; k < 7; ++k) {
        int idx = lane + k * 32;
        if (idx < N4v) {
            float4 v = row[idx];
            float4 h = sh[idx];
            s += v.x * h.x + v.y * h.y + v.z * h.z + v.w * h.w;
        }
    }
#pragma unroll
    for (int o = 16; o; o >>= 1) s += __shfl_xor_sync(0xffffffffu, s, o);
    if (lane == 0) out[b * Cv + p] = s * g_invnorm[b][p];
}

extern "C" void kernel_launch(void* const* d_in, const int* in_sizes, int n_in,
                              void* d_out, int out_size) {
    const float* x  = (const float*)d_in[0];   // [32,1024,28,28] f32
    const float* Wm = (const float*)d_in[1];   // [4,1,1024] f32
    float* out = (float*)d_out;                // [32,1024] f32

    static const int smem_bytes = 100 * 1024;  // occupancy limiter: 2 CTAs/SM
    cudaFuncSetAttribute(kAB, cudaFuncAttributeMaxDynamicSharedMemorySize, smem_bytes);

    kAB<<<dim3(32, CHUNKS), 256, smem_bytes>>>(x, Wm);
    kC<<<32, 224>>>();
    kD<<<dim3(32, 128), 256>>>(x, out);
}

// round 9
// speedup vs baseline: 1.6559x; 1.5000x over previous
#include <cuda_runtime.h>
#include <cstdint>

// Problem dims
#define Bv 32
#define Cv 1024
#define Nv 784
#define Mv 4
#define N4v 196      // Nv/4
#define GR 8         // rows per generation (= warps per block)
#define GEN 4        // generations per block
#define BROWS 32     // GR*GEN rows per block
#define CHUNKS 32    // Cv/BROWS

// Scratch (device globals — zero-initialized at load; kC restores zeros)
__device__ float  g_invnorm[Bv][Cv];
__device__ float4 g_t[Bv][Mv][N4v];   // RED-accumulated t (400 KB)
__device__ float4 g_h[Bv][N4v];       // h[b,n] = sum_m g/s

extern __shared__ float4 sdyn[];  // 2 buffers of GR*N4v float4 = 50176 B

// ---------------------------------------------------------------------------
// kAB: register-staged, double-buffered, ONE barrier per generation.
// Warp w owns row w of each 8-row generation:
//   prologue: LDG gen0 row -> regs, norm from regs, STS to buf0, swsc0.
//   loop g:   issue LDG gen g+1 (28 loads in flight/warp)
//             accumulate gen g from smem (128 FFMA -> hides the LDGs)
//             norm gen g+1 from regs (free), STS to other buf, swsc
//             __syncthreads()
// Flush accumulators with RED atomics into g_t.
// ---------------------------------------------------------------------------
__global__ void __launch_bounds__(256) kAB(const float* __restrict__ x,
                                           const float* __restrict__ Wm) {
    __shared__ float4 swsc[2][GR];
    float4* sbuf0 = sdyn;
    float4* sbuf1 = sdyn + GR * N4v;
    int b = blockIdx.x, ch = blockIdx.y;
    int p0 = ch * BROWS;
    int t = threadIdx.x;
    int warp = t >> 5, lane = t & 31;
    const float4* base = reinterpret_cast<const float4*>(x) + ((size_t)b * Cv + p0) * N4v;

    float4 v0, v1, v2, v3, v4, v5, v6;
    bool tail = (lane < 4);               // quad 192+lane valid only for lane<4

    // ---- prologue: load + norm + stage generation 0 ----
    {
        const float4* row = base + (size_t)warp * N4v;
        v0 = row[lane];        v1 = row[lane + 32];  v2 = row[lane + 64];
        v3 = row[lane + 96];   v4 = row[lane + 128]; v5 = row[lane + 160];
        v6 = tail ? row[lane + 192] : make_float4(0.f, 0.f, 0.f, 0.f);
        float s = v0.x*v0.x + v0.y*v0.y + v0.z*v0.z + v0.w*v0.w
                + v1.x*v1.x + v1.y*v1.y + v1.z*v1.z + v1.w*v1.w
                + v2.x*v2.x + v2.y*v2.y + v2.z*v2.z + v2.w*v2.w
                + v3.x*v3.x + v3.y*v3.y + v3.z*v3.z + v3.w*v3.w
                + v4.x*v4.x + v4.y*v4.y + v4.z*v4.z + v4.w*v4.w
                + v5.x*v5.x + v5.y*v5.y + v5.z*v5.z + v5.w*v5.w
                + v6.x*v6.x + v6.y*v6.y + v6.z*v6.z + v6.w*v6.w;
        float4* dst = sbuf0 + warp * N4v;
        dst[lane] = v0; dst[lane + 32] = v1; dst[lane + 64] = v2;
        dst[lane + 96] = v3; dst[lane + 128] = v4; dst[lane + 160] = v5;
        if (tail) dst[lane + 192] = v6;
#pragma unroll
        for (int o = 16; o; o >>= 1) s += __shfl_xor_sync(0xffffffffu, s, o);
        if (lane == 0) {
            float inv = 1.0f / fmaxf(sqrtf(s), 1e-10f);
            int p = p0 + warp;
            g_invnorm[b][p] = inv;
            float4 w;
            w.x = Wm[0 * Cv + p] * inv; w.y = Wm[1 * Cv + p] * inv;
            w.z = Wm[2 * Cv + p] * inv; w.w = Wm[3 * Cv + p] * inv;
            swsc[0][warp] = w;
        }
    }
    __syncthreads();

    float4 a0 = {0, 0, 0, 0}, a1 = a0, a2 = a0, a3 = a0;

#pragma unroll
    for (int g = 0; g < GEN; ++g) {
        // issue next generation's loads first (max overlap with accumulate)
        if (g + 1 < GEN) {
            const float4* row = base + (size_t)((g + 1) * GR + warp) * N4v;
            v0 = row[lane];        v1 = row[lane + 32];  v2 = row[lane + 64];
            v3 = row[lane + 96];   v4 = row[lane + 128]; v5 = row[lane + 160];
            v6 = tail ? row[lane + 192] : make_float4(0.f, 0.f, 0.f, 0.f);
        }

        // accumulate generation g from smem (long FFMA stretch hides LDGs)
        float4* cur = (g & 1) ? sbuf1 : sbuf0;
        if (t < N4v) {
#pragma unroll
            for (int r = 0; r < GR; ++r) {
                float4 w  = swsc[g & 1][r];
                float4 xv = cur[r * N4v + t];
                a0.x = fmaf(w.x, xv.x, a0.x); a0.y = fmaf(w.x, xv.y, a0.y);
                a0.z = fmaf(w.x, xv.z, a0.z); a0.w = fmaf(w.x, xv.w, a0.w);
                a1.x = fmaf(w.y, xv.x, a1.x); a1.y = fmaf(w.y, xv.y, a1.y);
                a1.z = fmaf(w.y, xv.z, a1.z); a1.w = fmaf(w.y, xv.w, a1.w);
                a2.x = fmaf(w.z, xv.x, a2.x); a2.y = fmaf(w.z, xv.y, a2.y);
                a2.z = fmaf(w.z, xv.z, a2.z); a2.w = fmaf(w.z, xv.w, a2.w);
                a3.x = fmaf(w.w, xv.x, a3.x); a3.y = fmaf(w.w, xv.y, a3.y);
                a3.z = fmaf(w.w, xv.z, a3.z); a3.w = fmaf(w.w, xv.w, a3.w);
            }
        }

        // norm + stage generation g+1 (regs already arrived under the FFMAs)
        if (g + 1 < GEN) {
            float s = v0.x*v0.x + v0.y*v0.y + v0.z*v0.z + v0.w*v0.w
                    + v1.x*v1.x + v1.y*v1.y + v1.z*v1.z + v1.w*v1.w
                    + v2.x*v2.x + v2.y*v2.y + v2.z*v2.z + v2.w*v2.w
                    + v3.x*v3.x + v3.y*v3.y + v3.z*v3.z + v3.w*v3.w
                    + v4.x*v4.x + v4.y*v4.y + v4.z*v4.z + v4.w*v4.w
                    + v5.x*v5.x + v5.y*v5.y + v5.z*v5.z + v5.w*v5.w
                    + v6.x*v6.x + v6.y*v6.y + v6.z*v6.z + v6.w*v6.w;
            float4* dst = ((g + 1) & 1 ? sbuf1 : sbuf0) + warp * N4v;
            dst[lane] = v0; dst[lane + 32] = v1; dst[lane + 64] = v2;
            dst[lane + 96] = v3; dst[lane + 128] = v4; dst[lane + 160] = v5;
            if (tail) dst[lane + 192] = v6;
#pragma unroll
            for (int o = 16; o; o >>= 1) s += __shfl_xor_sync(0xffffffffu, s, o);
            if (lane == 0) {
                float inv = 1.0f / fmaxf(sqrtf(s), 1e-10f);
                int p = p0 + (g + 1) * GR + warp;
                g_invnorm[b][p] = inv;
                float4 w;
                w.x = Wm[0 * Cv + p] * inv; w.y = Wm[1 * Cv + p] * inv;
                w.z = Wm[2 * Cv + p] * inv; w.w = Wm[3 * Cv + p] * inv;
                swsc[(g + 1) & 1][warp] = w;
            }
        }
        __syncthreads();
    }

    if (t < N4v) {
        float* d0 = reinterpret_cast<float*>(&g_t[b][0][t]);
        float* d1 = reinterpret_cast<float*>(&g_t[b][1][t]);
        float* d2 = reinterpret_cast<float*>(&g_t[b][2][t]);
        float* d3 = reinterpret_cast<float*>(&g_t[b][3][t]);
        atomicAdd(d0 + 0, a0.x); atomicAdd(d0 + 1, a0.y);
        atomicAdd(d0 + 2, a0.z); atomicAdd(d0 + 3, a0.w);
        atomicAdd(d1 + 0, a1.x); atomicAdd(d1 + 1, a1.y);
        atomicAdd(d1 + 2, a1.z); atomicAdd(d1 + 3, a1.w);
        atomicAdd(d2 + 0, a2.x); atomicAdd(d2 + 1, a2.y);
        atomicAdd(d2 + 2, a2.z); atomicAdd(d2 + 3, a2.w);
        atomicAdd(d3 + 0, a3.x); atomicAdd(d3 + 1, a3.y);
        atomicAdd(d3 + 2, a3.z); atomicAdd(d3 + 3, a3.w);
    }
}

// ---------------------------------------------------------------------------
// kC: one block per b, 224 threads. Sigmoid, per-model sum of g^2,
// h = sum_m g/s; then RE-ZERO g_t for the next call.
// ---------------------------------------------------------------------------
__global__ void __launch_bounds__(224) kC() {
    int b = blockIdx.x;
    int t = threadIdx.x;
    bool valid = (t < N4v);
    float4 gg0 = {0,0,0,0}, gg1 = gg0, gg2 = gg0, gg3 = gg0;
    if (valid) {
        float4 t0 = g_t[b][0][t], t1 = g_t[b][1][t];
        float4 t2 = g_t[b][2][t], t3 = g_t[b][3][t];
        auto sig4 = [](float4 v) {
            float4 r;
            r.x = 1.f / (1.f + __expf(-v.x));
            r.y = 1.f / (1.f + __expf(-v.y));
            r.z = 1.f / (1.f + __expf(-v.z));
            r.w = 1.f / (1.f + __expf(-v.w));
            return r;
        };
        gg0 = sig4(t0); gg1 = sig4(t1); gg2 = sig4(t2); gg3 = sig4(t3);
    }
    float s0 = gg0.x*gg0.x + gg0.y*gg0.y + gg0.z*gg0.z + gg0.w*gg0.w;
    float s1 = gg1.x*gg1.x + gg1.y*gg1.y + gg1.z*gg1.z + gg1.w*gg1.w;
    float s2 = gg2.x*gg2.x + gg2.y*gg2.y + gg2.z*gg2.z + gg2.w*gg2.w;
    float s3 = gg3.x*gg3.x + gg3.y*gg3.y + gg3.z*gg3.z + gg3.w*gg3.w;
#pragma unroll
    for (int o = 16; o; o >>= 1) {
        s0 += __shfl_xor_sync(0xffffffffu, s0, o);
        s1 += __shfl_xor_sync(0xffffffffu, s1, o);
        s2 += __shfl_xor_sync(0xffffffffu, s2, o);
        s3 += __shfl_xor_sync(0xffffffffu, s3, o);
    }
    __shared__ float sm[4];
    if (t < 4) sm[t] = 0.f;
    __syncthreads();
    if ((t & 31) == 0) {
        atomicAdd(&sm[0], s0);
        atomicAdd(&sm[1], s1);
        atomicAdd(&sm[2], s2);
        atomicAdd(&sm[3], s3);
    }
    __syncthreads();
    if (valid) {
        float i0 = 1.f / sm[0], i1 = 1.f / sm[1], i2 = 1.f / sm[2], i3 = 1.f / sm[3];
        float4 h;
        h.x = gg0.x*i0 + gg1.x*i1 + gg2.x*i2 + gg3.x*i3;
        h.y = gg0.y*i0 + gg1.y*i1 + gg2.y*i2 + gg3.y*i3;
        h.z = gg0.z*i0 + gg1.z*i1 + gg2.z*i2 + gg3.z*i3;
        h.w = gg0.w*i0 + gg1.w*i1 + gg2.w*i2 + gg3.w*i3;
        g_h[b][t] = h;
        float4 z = {0, 0, 0, 0};
        g_t[b][0][t] = z; g_t[b][1][t] = z;
        g_t[b][2][t] = z; g_t[b][3][t] = z;
    }
}

// ---------------------------------------------------------------------------
// kD: barrier-free final dot. Grid (32, 32), 512 threads = 16 warps; each
// warp streams TWO rows interleaved (14 x-loads + 7 h-loads in flight);
// h read via __ldg (L1-hot, shared by all warps of the block).
// ---------------------------------------------------------------------------
__global__ void __launch_bounds__(512) kD(const float* __restrict__ x,
                                          float* __restrict__ out) {
    int b = blockIdx.x;
    int warp = threadIdx.x >> 5, lane = threadIdx.x & 31;
    int p = (blockIdx.y << 5) + (warp << 1);   // rows p and p+1
    const float4* r0 = reinterpret_cast<const float4*>(x) + ((size_t)b * Cv + p) * N4v;
    const float4* r1 = r0 + N4v;
    const float4* hb = &g_h[b][0];
    float s0 = 0.f, s1 = 0.f;
#pragma unroll
    for (int k = 0; k < 6; ++k) {
        int idx = lane + k * 32;
        float4 a = r0[idx], c = r1[idx];
        float4 h = __ldg(hb + idx);
        s0 += a.x * h.x + a.y * h.y + a.z * h.z + a.w * h.w;
        s1 += c.x * h.x + c.y * h.y + c.z * h.z + c.w * h.w;
    }
    if (lane < 4) {
        int idx = 192 + lane;
        float4 a = r0[idx], c = r1[idx];
        float4 h = __ldg(hb + idx);
        s0 += a.x * h.x + a.y * h.y + a.z * h.z + a.w * h.w;
        s1 += c.x * h.x + c.y * h.y + c.z * h.z + c.w * h.w;
    }
#pragma unroll
    for (int o = 16; o; o >>= 1) {
        s0 += __shfl_xor_sync(0xffffffffu, s0, o);
        s1 += __shfl_xor_sync(0xffffffffu, s1, o);
    }
    if (lane == 0) {
        out[b * Cv + p]     = s0 * g_invnorm[b][p];
        out[b * Cv + p + 1] = s1 * g_invnorm[b][p + 1];
    }
}

extern "C" void kernel_launch(void* const* d_in, const int* in_sizes, int n_in,
                              void* d_out, int out_size) {
    const float* x  = (const float*)d_in[0];   // [32,1024,28,28] f32
    const float* Wm = (const float*)d_in[1];   // [4,1,1024] f32
    float* out = (float*)d_out;                // [32,1024] f32

    static const int smem_bytes = 2 * GR * N4v * sizeof(float4);  // 50176
    cudaFuncSetAttribute(kAB, cudaFuncAttributeMaxDynamicSharedMemorySize, smem_bytes);

    kAB<<<dim3(32, CHUNKS), 256, smem_bytes>>>(x, Wm);
    kC<<<32, 224>>>();
    kD<<<dim3(32, 32), 512>>>(x, out);
}

// round 10
// speedup vs baseline: 1.7320x; 1.0460x over previous
#include <cuda_runtime.h>
#include <cstdint>

// Problem dims
#define Bv 32
#define Cv 1024
#define Nv 784
#define Mv 4
#define N4v 196      // Nv/4
#define GR 8         // rows per generation
#define GEN 4        // generations per block
#define BROWS 32     // GR*GEN rows per block
#define CHUNKS 32    // Cv/BROWS
#define GSZ (GR * N4v)   // 1568 float4 per generation buffer

// Scratch (device globals — zero-initialized at load; kC restores zeros)
__device__ float  g_invnorm[Bv][Cv];
__device__ float4 g_t[Bv][Mv][N4v];   // RED-accumulated t (400 KB)
__device__ float4 g_h[Bv][N4v];       // h[b,n] = sum_m g/s

__device__ __forceinline__ void cp_async16(uint32_t saddr, const void* gaddr) {
    asm volatile("cp.async.cg.shared.global [%0], [%1], 16;\n" :: "r"(saddr), "l"(gaddr));
}
__device__ __forceinline__ void cp_commit() {
    asm volatile("cp.async.commit_group;\n");
}
template <int N>
__device__ __forceinline__ void cp_wait() {
    asm volatile("cp.async.wait_group %0;\n" :: "n"(N));
}

extern __shared__ float4 smem_dyn[];  // 2 * GSZ float4 = 50176 B

// ---------------------------------------------------------------------------
// kAB: block = (b, 32-row chunk), 4 generations of 8 rows, double-buffered
// cp.async (R3 structure, measured 25.2us). Per gen: warp-per-row norms from
// smem, then thread-per-quad 8-row accumulate. RED-atomic flush into g_t.
// ---------------------------------------------------------------------------
__global__ void __launch_bounds__(256) kAB(const float* __restrict__ x,
                                           const float* __restrict__ Wm) {
    __shared__ float4 swsc[GR];
    int b = blockIdx.x, ch = blockIdx.y;
    int p0 = ch * BROWS;
    int t = threadIdx.x;
    int warp = t >> 5, lane = t & 31;
    const float4* base = reinterpret_cast<const float4*>(x) + ((size_t)b * Cv + p0) * N4v;
    uint32_t sbase = (uint32_t)__cvta_generic_to_shared(smem_dyn);

    // prefetch generation 0 into buffer 0
#pragma unroll
    for (int k = 0; k < 7; ++k) {
        int i = t + k * 256;
        if (i < GSZ) cp_async16(sbase + i * 16u, base + i);
    }
    cp_commit();

    float4 a0 = {0, 0, 0, 0}, a1 = a0, a2 = a0, a3 = a0;

#pragma unroll
    for (int g = 0; g < GEN; ++g) {
        if (g + 1 < GEN) {
            uint32_t sb = sbase + ((g + 1) & 1) * (GSZ * 16u);
            const float4* gb = base + (g + 1) * GSZ;
#pragma unroll
            for (int k = 0; k < 7; ++k) {
                int i = t + k * 256;
                if (i < GSZ) cp_async16(sb + i * 16u, gb + i);
            }
            cp_commit();
            cp_wait<1>();   // current generation's data is ready
        } else {
            cp_wait<0>();
        }
        __syncthreads();

        float4* cur = smem_dyn + (g & 1) * GSZ;

        // norms: warp w handles row w (8 warps, 8 rows)
        {
            float s = 0.f;
#pragma unroll
            for (int k = 0; k < 7; ++k) {
                int idx = lane + k * 32;
                if (idx < N4v) {
                    float4 v = cur[warp * N4v + idx];
                    s += v.x * v.x + v.y * v.y + v.z * v.z + v.w * v.w;
                }
            }
#pragma unroll
            for (int o = 16; o; o >>= 1) s += __shfl_xor_sync(0xffffffffu, s, o);
            if (lane == 0) {
                float inv = 1.0f / fmaxf(sqrtf(s), 1e-10f);
                int p = p0 + g * GR + warp;
                g_invnorm[b][p] = inv;
                float4 w;
                w.x = Wm[0 * Cv + p] * inv;
                w.y = Wm[1 * Cv + p] * inv;
                w.z = Wm[2 * Cv + p] * inv;
                w.w = Wm[3 * Cv + p] * inv;
                swsc[warp] = w;
            }
        }
        __syncthreads();

        // t-accumulation for this generation's 8 rows
        if (t < N4v) {
#pragma unroll
            for (int r = 0; r < GR; ++r) {
                float4 w  = swsc[r];
                float4 xv = cur[r * N4v + t];
                a0.x = fmaf(w.x, xv.x, a0.x); a0.y = fmaf(w.x, xv.y, a0.y);
                a0.z = fmaf(w.x, xv.z, a0.z); a0.w = fmaf(w.x, xv.w, a0.w);
                a1.x = fmaf(w.y, xv.x, a1.x); a1.y = fmaf(w.y, xv.y, a1.y);
                a1.z = fmaf(w.y, xv.z, a1.z); a1.w = fmaf(w.y, xv.w, a1.w);
                a2.x = fmaf(w.z, xv.x, a2.x); a2.y = fmaf(w.z, xv.y, a2.y);
                a2.z = fmaf(w.z, xv.z, a2.z); a2.w = fmaf(w.z, xv.w, a2.w);
                a3.x = fmaf(w.w, xv.x, a3.x); a3.y = fmaf(w.w, xv.y, a3.y);
                a3.z = fmaf(w.w, xv.z, a3.z); a3.w = fmaf(w.w, xv.w, a3.w);
            }
        }
        __syncthreads();  // buffer fully consumed before next prefetch overwrites
    }

    if (t < N4v) {
        float* d0 = reinterpret_cast<float*>(&g_t[b][0][t]);
        float* d1 = reinterpret_cast<float*>(&g_t[b][1][t]);
        float* d2 = reinterpret_cast<float*>(&g_t[b][2][t]);
        float* d3 = reinterpret_cast<float*>(&g_t[b][3][t]);
        atomicAdd(d0 + 0, a0.x); atomicAdd(d0 + 1, a0.y);
        atomicAdd(d0 + 2, a0.z); atomicAdd(d0 + 3, a0.w);
        atomicAdd(d1 + 0, a1.x); atomicAdd(d1 + 1, a1.y);
        atomicAdd(d1 + 2, a1.z); atomicAdd(d1 + 3, a1.w);
        atomicAdd(d2 + 0, a2.x); atomicAdd(d2 + 1, a2.y);
        atomicAdd(d2 + 2, a2.z); atomicAdd(d2 + 3, a2.w);
        atomicAdd(d3 + 0, a3.x); atomicAdd(d3 + 1, a3.y);
        atomicAdd(d3 + 2, a3.z); atomicAdd(d3 + 3, a3.w);
    }
}

// ---------------------------------------------------------------------------
// kC: one block per b, 224 threads. Sigmoid, per-model sum of g^2,
// h = sum_m g/s; then RE-ZERO g_t for the next call.
// ---------------------------------------------------------------------------
__global__ void __launch_bounds__(224) kC() {
    int b = blockIdx.x;
    int t = threadIdx.x;
    bool valid = (t < N4v);
    float4 gg0 = {0,0,0,0}, gg1 = gg0, gg2 = gg0, gg3 = gg0;
    if (valid) {
        float4 t0 = g_t[b][0][t], t1 = g_t[b][1][t];
        float4 t2 = g_t[b][2][t], t3 = g_t[b][3][t];
        auto sig4 = [](float4 v) {
            float4 r;
            r.x = 1.f / (1.f + __expf(-v.x));
            r.y = 1.f / (1.f + __expf(-v.y));
            r.z = 1.f / (1.f + __expf(-v.z));
            r.w = 1.f / (1.f + __expf(-v.w));
            return r;
        };
        gg0 = sig4(t0); gg1 = sig4(t1); gg2 = sig4(t2); gg3 = sig4(t3);
    }
    float s0 = gg0.x*gg0.x + gg0.y*gg0.y + gg0.z*gg0.z + gg0.w*gg0.w;
    float s1 = gg1.x*gg1.x + gg1.y*gg1.y + gg1.z*gg1.z + gg1.w*gg1.w;
    float s2 = gg2.x*gg2.x + gg2.y*gg2.y + gg2.z*gg2.z + gg2.w*gg2.w;
    float s3 = gg3.x*gg3.x + gg3.y*gg3.y + gg3.z*gg3.z + gg3.w*gg3.w;
#pragma unroll
    for (int o = 16; o; o >>= 1) {
        s0 += __shfl_xor_sync(0xffffffffu, s0, o);
        s1 += __shfl_xor_sync(0xffffffffu, s1, o);
        s2 += __shfl_xor_sync(0xffffffffu, s2, o);
        s3 += __shfl_xor_sync(0xffffffffu, s3, o);
    }
    __shared__ float sm[4];
    if (t < 4) sm[t] = 0.f;
    __syncthreads();
    if ((t & 31) == 0) {
        atomicAdd(&sm[0], s0);
        atomicAdd(&sm[1], s1);
        atomicAdd(&sm[2], s2);
        atomicAdd(&sm[3], s3);
    }
    __syncthreads();
    if (valid) {
        float i0 = 1.f / sm[0], i1 = 1.f / sm[1], i2 = 1.f / sm[2], i3 = 1.f / sm[3];
        float4 h;
        h.x = gg0.x*i0 + gg1.x*i1 + gg2.x*i2 + gg3.x*i3;
        h.y = gg0.y*i0 + gg1.y*i1 + gg2.y*i2 + gg3.y*i3;
        h.z = gg0.z*i0 + gg1.z*i1 + gg2.z*i2 + gg3.z*i3;
        h.w = gg0.w*i0 + gg1.w*i1 + gg2.w*i2 + gg3.w*i3;
        g_h[b][t] = h;
        float4 z = {0, 0, 0, 0};
        g_t[b][0][t] = z; g_t[b][1][t] = z;
        g_t[b][2][t] = z; g_t[b][3][t] = z;
    }
}

// ---------------------------------------------------------------------------
// kD: barrier-free final dot (R8, proven). Grid (32, 32), 512 threads; each
// warp streams TWO rows interleaved; h via __ldg (L1-hot).
// ---------------------------------------------------------------------------
__global__ void __launch_bounds__(512) kD(const float* __restrict__ x,
                                          float* __restrict__ out) {
    int b = blockIdx.x;
    int warp = threadIdx.x >> 5, lane = threadIdx.x & 31;
    int p = (blockIdx.y << 5) + (warp << 1);   // rows p and p+1
    const float4* r0 = reinterpret_cast<const float4*>(x) + ((size_t)b * Cv + p) * N4v;
    const float4* r1 = r0 + N4v;
    const float4* hb = &g_h[b][0];
    float s0 = 0.f, s1 = 0.f;
#pragma unroll
    for (int k = 0; k < 6; ++k) {
        int idx = lane + k * 32;
        float4 a = r0[idx], c = r1[idx];
        float4 h = __ldg(hb + idx);
        s0 += a.x * h.x + a.y * h.y + a.z * h.z + a.w * h.w;
        s1 += c.x * h.x + c.y * h.y + c.z * h.z + c.w * h.w;
    }
    if (lane < 4) {
        int idx = 192 + lane;
        float4 a = r0[idx], c = r1[idx];
        float4 h = __ldg(hb + idx);
        s0 += a.x * h.x + a.y * h.y + a.z * h.z + a.w * h.w;
        s1 += c.x * h.x + c.y * h.y + c.z * h.z + c.w * h.w;
    }
#pragma unroll
    for (int o = 16; o; o >>= 1) {
        s0 += __shfl_xor_sync(0xffffffffu, s0, o);
        s1 += __shfl_xor_sync(0xffffffffu, s1, o);
    }
    if (lane == 0) {
        out[b * Cv + p]     = s0 * g_invnorm[b][p];
        out[b * Cv + p + 1] = s1 * g_invnorm[b][p + 1];
    }
}

extern "C" void kernel_launch(void* const* d_in, const int* in_sizes, int n_in,
                              void* d_out, int out_size) {
    const float* x  = (const float*)d_in[0];   // [32,1024,28,28] f32
    const float* Wm = (const float*)d_in[1];   // [4,1,1024] f32
    float* out = (float*)d_out;                // [32,1024] f32

    static const int smem_bytes = 2 * GSZ * sizeof(float4);  // 50176
    cudaFuncSetAttribute(kAB, cudaFuncAttributeMaxDynamicSharedMemorySize, smem_bytes);

    kAB<<<dim3(32, CHUNKS), 256, smem_bytes>>>(x, Wm);
    kC<<<32, 224>>>();
    kD<<<dim3(32, 32), 512>>>(x, out);
}